// round 11
// baseline (speedup 1.0000x reference)
#include <cuda_runtime.h>
#include <cstdint>

#define B_    16
#define N_    131072
#define NB    8                   // CTAs per cluster = slices per batch
#define PPB   (N_ / NB)           // 16384 points per CTA
#define TPB   1024
#define NPAIR (PPB / (TPB * 2))   // 8 pairs (16 points) per thread
#define NPT1  1024
#define OUTW  336                 // 256 + 64 + 16

__device__ __forceinline__ unsigned long long kmax64(unsigned long long a,
                                                     unsigned long long b) {
    return a > b ? a : b;
}
__device__ __forceinline__ unsigned cluster_rank() {
    unsigned r; asm("mov.u32 %0, %%cluster_ctarank;" : "=r"(r)); return r;
}
__device__ __forceinline__ void cluster_sync_() {
    asm volatile("barrier.cluster.arrive.aligned;" ::: "memory");
    asm volatile("barrier.cluster.wait.aligned;" ::: "memory");
}
__device__ __forceinline__ uint32_t mapa_sh(uint32_t local_addr, unsigned rank) {
    uint32_t r;
    asm("mapa.shared::cluster.u32 %0, %1, %2;" : "=r"(r) : "r"(local_addr), "r"(rank));
    return r;
}
__device__ __forceinline__ void st_cluster_u64(uint32_t addr, unsigned long long v) {
    asm volatile("st.shared::cluster.b64 [%0], %1;" :: "r"(addr), "l"(v) : "memory");
}
__device__ __forceinline__ void st_cluster_u32(uint32_t addr, uint32_t v) {
    asm volatile("st.shared::cluster.b32 [%0], %1;" :: "r"(addr), "r"(v) : "memory");
}
__device__ __forceinline__ void mbar_arrive_rel_cluster(uint32_t mbar_addr) {
    asm volatile("mbarrier.arrive.release.cluster.shared::cluster.b64 _, [%0];"
                 :: "r"(mbar_addr) : "memory");
}
__device__ __forceinline__ void mbar_wait_parity_cluster(uint32_t mbar, uint32_t parity) {
    asm volatile(
        "{\n\t"
        ".reg .pred P;\n\t"
        "W_%=:\n\t"
        "mbarrier.try_wait.parity.acquire.cluster.shared::cta.b64 P, [%0], %1;\n\t"
        "@!P bra W_%=;\n\t"
        "}" :: "r"(mbar), "r"(parity) : "memory");
}

// ---- packed f32x2 helpers (lanes bit-identical to scalar .rn ops) -----------
__device__ __forceinline__ unsigned long long pk2(float lo, float hi) {
    unsigned long long r;
    asm("mov.b64 %0, {%1, %2};" : "=l"(r) : "f"(lo), "f"(hi)); return r;
}
__device__ __forceinline__ void upk2(unsigned long long v, float& lo, float& hi) {
    asm("mov.b64 {%0, %1}, %2;" : "=f"(lo), "=f"(hi) : "l"(v));
}
__device__ __forceinline__ unsigned long long add2(unsigned long long a, unsigned long long b) {
    unsigned long long r;
    asm("add.rn.f32x2 %0, %1, %2;" : "=l"(r) : "l"(a), "l"(b)); return r;
}
__device__ __forceinline__ unsigned long long mul2(unsigned long long a, unsigned long long b) {
    unsigned long long r;
    asm("mul.rn.f32x2 %0, %1, %2;" : "=l"(r) : "l"(a), "l"(b)); return r;
}

// verified scalar form (rel_err 0.0): ((dx^2 + dy^2) + dz^2), no contraction
__device__ __forceinline__ float sqdist(float xx, float yy, float zz,
                                        float px, float py, float pz) {
    float dx = __fsub_rn(xx, px);
    float dy = __fsub_rn(yy, py);
    float dz = __fsub_rn(zz, pz);
    return __fadd_rn(__fadd_rn(__fmul_rn(dx, dx), __fmul_rn(dy, dy)),
                     __fmul_rn(dz, dz));
}

// ======================= single fused kernel =================================
__global__ void __launch_bounds__(TPB, 1) __cluster_dims__(NB, 1, 1)
fps_fused(const float* __restrict__ x, float* __restrict__ out) {
    const unsigned rank = cluster_rank();
    const int b = blockIdx.x / NB;
    extern __shared__ float smemf[];            // SoA: x | y | z (192 KB)
    float* sxx = smemf;
    float* syy = smemf + PPB;
    float* szz = smemf + 2 * PPB;

    __shared__ unsigned long long xkey[2][NB];  // exchanged keys
    __shared__ unsigned long long xxy[2][NB];   // exchanged (x,y) packed
    __shared__ float xz[2][NB];                 // exchanged z
    __shared__ unsigned long long wkey[2][TPB / 32];
    __shared__ unsigned long long mbar;
    // rest-phase (rank 0 only) winner stash + working arrays (~26 KB static)
    __shared__ float sxr[NPT1], syr[NPT1], szr[NPT1], sdist[NPT1];
    __shared__ int   gidr[NPT1];
    __shared__ int   sel[256];
    __shared__ float txr[256], tyr[256], tzr[256];
    __shared__ int   tgr[256];

    const float* xb = x + (size_t)b * (N_ * 3);
    const int base = (int)rank * PPB;
    const int tid = threadIdx.x;
    const int lane = tid & 31;
    const int w    = tid >> 5;

    // AoS global -> SoA smem
    for (int i = tid; i < PPB; i += TPB) {
        const float* p = xb + (size_t)(base + i) * 3;
        sxx[i] = p[0]; syy[i] = p[1]; szz[i] = p[2];
    }
    if (tid == 0) {
        asm volatile("mbarrier.init.shared.b64 [%0], %1;"
                     :: "r"((uint32_t)__cvta_generic_to_shared(&mbar)), "r"(NB)
                     : "memory");
    }
    __syncthreads();
    cluster_sync_();   // all mbarriers live before any remote arrive

    float dist[2 * NPAIR];
#pragma unroll
    for (int j = 0; j < 2 * NPAIR; j++) dist[j] = 1e10f;

    // first sampled point: global index 0
    float px = xb[0], py = xb[1], pz = xb[2];
    if (rank == 0 && tid == 0) {
        gidr[0] = 0; sxr[0] = px; syr[0] = py; szr[0] = pz;
    }

    const int t2 = tid * 2;
    const uint32_t mbar_lcl = (uint32_t)__cvta_generic_to_shared(&mbar);

    for (int it = 0; it < NPT1 - 1; ++it) {
        const int buf = it & 1;
        const unsigned long long npx2 = pk2(-px, -px);
        const unsigned long long npy2 = pk2(-py, -py);
        const unsigned long long npz2 = pk2(-pz, -pz);

        // ---- distance update: pure min, NO serial argmax chain --------------
#pragma unroll
        for (int p = 0; p < NPAIR; ++p) {
            const int e = p * (TPB * 2) + t2;           // 2 consecutive points
            float2 xv = *(const float2*)(sxx + e);
            float2 yv = *(const float2*)(syy + e);
            float2 zv = *(const float2*)(szz + e);
            unsigned long long dx = add2(pk2(xv.x, xv.y), npx2);
            unsigned long long dy = add2(pk2(yv.x, yv.y), npy2);
            unsigned long long dz = add2(pk2(zv.x, zv.y), npz2);
            unsigned long long ss = add2(add2(mul2(dx, dx), mul2(dy, dy)), mul2(dz, dz));
            float d0, d1; upk2(ss, d0, d1);
            dist[2 * p + 0] = fminf(dist[2 * p + 0], d0);
            dist[2 * p + 1] = fminf(dist[2 * p + 1], d1);
        }
        // ---- max via tree (depth 4, parallel) -------------------------------
        float t8[8];
#pragma unroll
        for (int k = 0; k < 8; ++k) t8[k] = fmaxf(dist[2 * k], dist[2 * k + 1]);
        float t4a = fmaxf(fmaxf(t8[0], t8[1]), fmaxf(t8[2], t8[3]));
        float t4b = fmaxf(fmaxf(t8[4], t8[5]), fmaxf(t8[6], t8[7]));
        float m = fmaxf(t4a, t4b);
        // ---- first (smallest-k) index equal to m: descending pred-writes ----
        int kk = 0;
#pragma unroll
        for (int k = 2 * NPAIR - 1; k >= 0; --k)
            if (dist[k] == m) kk = k;                    // last write = smallest k
        const int e_win = (kk >> 1) * (TPB * 2) + t2 + (kk & 1);

        unsigned long long key =
            ((unsigned long long)__float_as_uint(m) << 32) | (unsigned)~(base + e_win);
#pragma unroll
        for (int o = 16; o; o >>= 1)
            key = kmax64(key, __shfl_xor_sync(0xffffffffu, key, o));
        if (lane == 0) wkey[buf][w] = key;
        __syncthreads();                                  // only block bar / iter

        if (w == 0) {                                     // 32 warp keys -> best
            unsigned long long k2 = wkey[buf][lane];
#pragma unroll
            for (int o = 16; o; o >>= 1)
                k2 = kmax64(k2, __shfl_xor_sync(0xffffffffu, k2, o));
            const int loc = (int)((~(unsigned)k2) & (N_ - 1)) - base;
            const float wxv = sxx[loc], wyv = syy[loc], wzv = szz[loc];
            if (lane < NB) {
                const uint32_t ka = mapa_sh((uint32_t)__cvta_generic_to_shared(&xkey[buf][rank]), (unsigned)lane);
                const uint32_t ca = mapa_sh((uint32_t)__cvta_generic_to_shared(&xxy[buf][rank]),  (unsigned)lane);
                const uint32_t za = mapa_sh((uint32_t)__cvta_generic_to_shared(&xz[buf][rank]),   (unsigned)lane);
                st_cluster_u64(ka, k2);
                st_cluster_u64(ca, pk2(wxv, wyv));
                st_cluster_u32(za, __float_as_uint(wzv));
                mbar_arrive_rel_cluster(mapa_sh(mbar_lcl, (unsigned)lane));
            }
        }
        mbar_wait_parity_cluster(mbar_lcl, (uint32_t)buf);

        unsigned long long best = xkey[buf][0];
        int br = 0;
#pragma unroll
        for (int k = 1; k < NB; k++) {
            unsigned long long v = xkey[buf][k];
            if (v > best) { best = v; br = k; }
        }
        float nx, ny; upk2(xxy[buf][br], nx, ny);
        px = nx; py = ny; pz = xz[buf][br];
        if (rank == 0 && tid == 0) {                      // stash winner locally
            gidr[it + 1] = (int)((~(unsigned)best) & (N_ - 1));
            sxr[it + 1] = px; syr[it + 1] = py; szr[it + 1] = pz;
        }
    }
    cluster_sync_();          // no CTA exits while peers may still target its smem
    if (rank != 0) return;    // peers done; rank 0 runs stages 2-4 alone

    // ---------------- stages 2-4: 1024 -> 256 -> 64 -> 16 (local smem) -------
    float* ob = out + b * OUTW;
    int n = NPT1, offs = 0;
    const int cnts[3] = {256, 64, 16};
    __syncthreads();          // gidr/sxr... visible (tid0 wrote during loop)

    for (int st = 0; st < 3; ++st) {
        const int npt = cnts[st];
        for (int i = tid; i < n; i += TPB) sdist[i] = 1e10f;
        if (tid == 0) { sel[0] = 0; ob[offs] = (float)gidr[0]; }
        __syncthreads();
        float qx = sxr[0], qy = syr[0], qz = szr[0];

        for (int it = 0; it < npt - 1; ++it) {
            const int buf = it & 1;
            unsigned long long key = 0ull;
            for (int i = tid; i < n; i += TPB) {
                float d  = sqdist(sxr[i], syr[i], szr[i], qx, qy, qz);
                float nd = fminf(sdist[i], d);
                sdist[i] = nd;
                unsigned long long k =
                    ((unsigned long long)__float_as_uint(nd) << 32) | (unsigned)~i;
                key = kmax64(key, k);
            }
#pragma unroll
            for (int o = 16; o; o >>= 1)
                key = kmax64(key, __shfl_xor_sync(0xffffffffu, key, o));
            if (lane == 0) wkey[buf][w] = key;
            __syncthreads();
            unsigned long long best = wkey[buf][0];
#pragma unroll
            for (int ww = 1; ww < TPB / 32; ww++) best = kmax64(best, wkey[buf][ww]);
            const int loc = (int)((~(unsigned)best) & (NPT1 - 1));
            if (tid == 0) {
                sel[it + 1] = loc;
                ob[offs + it + 1] = (float)gidr[loc];     // float32 output
            }
            qx = sxr[loc]; qy = syr[loc]; qz = szr[loc];  // broadcast LDS
        }
        __syncthreads();

        for (int i = tid; i < npt; i += TPB) {
            int s2 = sel[i];
            txr[i] = sxr[s2]; tyr[i] = syr[s2]; tzr[i] = szr[s2]; tgr[i] = gidr[s2];
        }
        __syncthreads();
        for (int i = tid; i < npt; i += TPB) {
            sxr[i] = txr[i]; syr[i] = tyr[i]; szr[i] = tzr[i]; gidr[i] = tgr[i];
        }
        __syncthreads();
        n = npt;
        offs += npt;   // 0 -> 256 -> 320
    }
}

// ---------------- launch ----------------
extern "C" void kernel_launch(void* const* d_in, const int* in_sizes, int n_in,
                              void* d_out, int out_size) {
    (void)in_sizes; (void)n_in; (void)out_size;
    const float* x = (const float*)d_in[0];
    float* out = (float*)d_out;

    cudaFuncSetAttribute(fps_fused,
                         cudaFuncAttributeMaxDynamicSharedMemorySize,
                         PPB * 3 * sizeof(float));

    fps_fused<<<B_ * NB, TPB, PPB * 3 * sizeof(float)>>>(x, out);
}

// round 12
// speedup vs baseline: 1.1809x; 1.1809x over previous
#include <cuda_runtime.h>
#include <cstdint>

#define B_    16
#define N_    131072
#define NB    8                   // CTAs per cluster = slices per batch
#define PPB   (N_ / NB)           // 16384 points per CTA
#define TPB   512
#define NQ    (PPB / (TPB * 4))   // 8 quads (32 points) per thread
#define NPT1  1024
#define OUTW  336                 // 256 + 64 + 16

typedef unsigned long long ull;

__device__ __forceinline__ ull kmax64(ull a, ull b) { return a > b ? a : b; }
__device__ __forceinline__ unsigned cluster_rank() {
    unsigned r; asm("mov.u32 %0, %%cluster_ctarank;" : "=r"(r)); return r;
}
__device__ __forceinline__ void cluster_sync_() {
    asm volatile("barrier.cluster.arrive.aligned;" ::: "memory");
    asm volatile("barrier.cluster.wait.aligned;" ::: "memory");
}
__device__ __forceinline__ uint32_t mapa_sh(uint32_t local_addr, unsigned rank) {
    uint32_t r;
    asm("mapa.shared::cluster.u32 %0, %1, %2;" : "=r"(r) : "r"(local_addr), "r"(rank));
    return r;
}
__device__ __forceinline__ void st_cluster_u64(uint32_t addr, ull v) {
    asm volatile("st.shared::cluster.b64 [%0], %1;" :: "r"(addr), "l"(v) : "memory");
}
__device__ __forceinline__ void st_cluster_u32(uint32_t addr, uint32_t v) {
    asm volatile("st.shared::cluster.b32 [%0], %1;" :: "r"(addr), "r"(v) : "memory");
}
__device__ __forceinline__ void mbar_arrive_rel_cluster(uint32_t mbar_addr) {
    asm volatile("mbarrier.arrive.release.cluster.shared::cluster.b64 _, [%0];"
                 :: "r"(mbar_addr) : "memory");
}
__device__ __forceinline__ void mbar_wait_parity_cluster(uint32_t mbar, uint32_t parity) {
    asm volatile(
        "{\n\t"
        ".reg .pred P;\n\t"
        "W_%=:\n\t"
        "mbarrier.try_wait.parity.acquire.cluster.shared::cta.b64 P, [%0], %1;\n\t"
        "@!P bra W_%=;\n\t"
        "}" :: "r"(mbar), "r"(parity) : "memory");
}

// ---- packed f32x2 helpers (lanes bit-identical to scalar .rn ops) -----------
__device__ __forceinline__ ull pk2(float lo, float hi) {
    ull r; asm("mov.b64 %0, {%1, %2};" : "=l"(r) : "f"(lo), "f"(hi)); return r;
}
__device__ __forceinline__ void upk2(ull v, float& lo, float& hi) {
    asm("mov.b64 {%0, %1}, %2;" : "=f"(lo), "=f"(hi) : "l"(v));
}
__device__ __forceinline__ ull add2(ull a, ull b) {
    ull r; asm("add.rn.f32x2 %0, %1, %2;" : "=l"(r) : "l"(a), "l"(b)); return r;
}
__device__ __forceinline__ ull mul2(ull a, ull b) {
    ull r; asm("mul.rn.f32x2 %0, %1, %2;" : "=l"(r) : "l"(a), "l"(b)); return r;
}

// verified scalar form (rel_err 0.0): ((dx^2 + dy^2) + dz^2), no contraction
__device__ __forceinline__ float sqdist(float xx, float yy, float zz,
                                        float px, float py, float pz) {
    float dx = __fsub_rn(xx, px);
    float dy = __fsub_rn(yy, py);
    float dz = __fsub_rn(zz, pz);
    return __fadd_rn(__fadd_rn(__fmul_rn(dx, dx), __fmul_rn(dy, dy)),
                     __fmul_rn(dz, dz));
}

// ======================= single fused kernel =================================
__global__ void __launch_bounds__(TPB, 1) __cluster_dims__(NB, 1, 1)
fps_fused(const float* __restrict__ x, float* __restrict__ out) {
    const unsigned rank = cluster_rank();
    const int b = blockIdx.x / NB;
    extern __shared__ float smemf[];            // SoA: x | y | z (192 KB)
    float* sxx = smemf;
    float* syy = smemf + PPB;
    float* szz = smemf + 2 * PPB;

    __shared__ __align__(16) ull xkey[2][NB];   // exchanged keys
    __shared__ ull xxy[2][NB];                  // exchanged (x,y) packed
    __shared__ float xz[2][NB];                 // exchanged z
    __shared__ __align__(16) ull wkey[2][TPB / 32];
    __shared__ ull mbar;
    // rank-0 epilogue arrays (~26 KB static)
    __shared__ float sxr[NPT1], syr[NPT1], szr[NPT1], sdist[NPT1];
    __shared__ int   gidr[NPT1];
    __shared__ int   sel[256];
    __shared__ float txr[256], tyr[256], tzr[256];
    __shared__ int   tgr[256];

    const float* xb = x + (size_t)b * (N_ * 3);
    const int base = (int)rank * PPB;
    const int tid = threadIdx.x;
    const int lane = tid & 31;
    const int w    = tid >> 5;

    // AoS global -> SoA smem
    for (int i = tid; i < PPB; i += TPB) {
        const float* p = xb + (size_t)(base + i) * 3;
        sxx[i] = p[0]; syy[i] = p[1]; szz[i] = p[2];
    }
    if (tid == 0) {
        asm volatile("mbarrier.init.shared.b64 [%0], %1;"
                     :: "r"((uint32_t)__cvta_generic_to_shared(&mbar)), "r"(NB)
                     : "memory");
    }
    __syncthreads();
    cluster_sync_();   // all mbarriers live before any remote arrive

    float dist[4 * NQ];
#pragma unroll
    for (int j = 0; j < 4 * NQ; j++) dist[j] = 1e10f;

    // first sampled point: global index 0
    float px = xb[0], py = xb[1], pz = xb[2];
    if (rank == 0 && tid == 0) {
        gidr[0] = 0; sxr[0] = px; syr[0] = py; szr[0] = pz;
    }

    const int t4 = tid * 4;
    const uint32_t mbar_lcl = (uint32_t)__cvta_generic_to_shared(&mbar);

    for (int it = 0; it < NPT1 - 1; ++it) {
        const int buf = it & 1;
        const ull npx2 = pk2(-px, -px);
        const ull npy2 = pk2(-py, -py);
        const ull npz2 = pk2(-pz, -pz);

        // ---- distance update: packed pairs straight from LDS.128 ------------
#pragma unroll
        for (int q = 0; q < NQ; ++q) {
            const int lp = q * (TPB * 4) + t4;          // 4 consecutive points
            ulonglong2 xq = *(const ulonglong2*)(sxx + lp);
            ulonglong2 yq = *(const ulonglong2*)(syy + lp);
            ulonglong2 zq = *(const ulonglong2*)(szz + lp);
            ull dxa = add2(xq.x, npx2), dxb = add2(xq.y, npx2);
            ull dya = add2(yq.x, npy2), dyb = add2(yq.y, npy2);
            ull dza = add2(zq.x, npz2), dzb = add2(zq.y, npz2);
            ull ssa = add2(add2(mul2(dxa, dxa), mul2(dya, dya)), mul2(dza, dza));
            ull ssb = add2(add2(mul2(dxb, dxb), mul2(dyb, dyb)), mul2(dzb, dzb));
            float d0, d1, d2, d3;
            upk2(ssa, d0, d1);
            upk2(ssb, d2, d3);
            const int k = q * 4;
            dist[k + 0] = fminf(dist[k + 0], d0);
            dist[k + 1] = fminf(dist[k + 1], d1);
            dist[k + 2] = fminf(dist[k + 2], d2);
            dist[k + 3] = fminf(dist[k + 3], d3);
        }
        // ---- max via tree (depth 5, parallel) -------------------------------
        float t16[16];
#pragma unroll
        for (int k = 0; k < 16; ++k) t16[k] = fmaxf(dist[2 * k], dist[2 * k + 1]);
        float t8[8];
#pragma unroll
        for (int k = 0; k < 8; ++k) t8[k] = fmaxf(t16[2 * k], t16[2 * k + 1]);
        float ta = fmaxf(fmaxf(t8[0], t8[1]), fmaxf(t8[2], t8[3]));
        float tb = fmaxf(fmaxf(t8[4], t8[5]), fmaxf(t8[6], t8[7]));
        float m = fmaxf(ta, tb);
        // ---- first (smallest-k) element equal to m (verified in R11) --------
        int kk = 0;
#pragma unroll
        for (int k = 4 * NQ - 1; k >= 0; --k)
            if (dist[k] == m) kk = k;                   // last write = smallest k
        const int e_win = (kk >> 2) * (TPB * 4) + t4 + (kk & 3);

        ull key = ((ull)__float_as_uint(m) << 32) | (unsigned)~(base + e_win);
#pragma unroll
        for (int o = 16; o; o >>= 1)
            key = kmax64(key, __shfl_xor_sync(0xffffffffu, key, o));
        if (lane == 0) wkey[buf][w] = key;
        __syncthreads();                                 // only block bar / iter

        if (w == 0) {                                    // 16 warp keys -> best
            ull k2 = wkey[buf][lane & 15];
#pragma unroll
            for (int o = 8; o; o >>= 1)
                k2 = kmax64(k2, __shfl_xor_sync(0xffffffffu, k2, o));
            const int loc = (int)((~(unsigned)k2) & (N_ - 1)) - base;
            const float wxv = sxx[loc], wyv = syy[loc], wzv = szz[loc];
            if (lane < NB) {
                const uint32_t ka = mapa_sh((uint32_t)__cvta_generic_to_shared(&xkey[buf][rank]), (unsigned)lane);
                const uint32_t ca = mapa_sh((uint32_t)__cvta_generic_to_shared(&xxy[buf][rank]),  (unsigned)lane);
                const uint32_t za = mapa_sh((uint32_t)__cvta_generic_to_shared(&xz[buf][rank]),   (unsigned)lane);
                st_cluster_u64(ka, k2);
                st_cluster_u64(ca, pk2(wxv, wyv));
                st_cluster_u32(za, __float_as_uint(wzv));
                mbar_arrive_rel_cluster(mapa_sh(mbar_lcl, (unsigned)lane));
            }
        }
        mbar_wait_parity_cluster(mbar_lcl, (uint32_t)buf);

        // ---- reduce 8 exchanged keys: LDS.128 x4 + depth-3 tree -------------
        const ulonglong2* xk = (const ulonglong2*)&xkey[buf][0];
        ulonglong2 p01 = xk[0], p23 = xk[1], p45 = xk[2], p67 = xk[3];
        ull m01 = kmax64(p01.x, p01.y); int i01 = (p01.y > p01.x) ? 1 : 0;
        ull m23 = kmax64(p23.x, p23.y); int i23 = (p23.y > p23.x) ? 3 : 2;
        ull m45 = kmax64(p45.x, p45.y); int i45 = (p45.y > p45.x) ? 5 : 4;
        ull m67 = kmax64(p67.x, p67.y); int i67 = (p67.y > p67.x) ? 7 : 6;
        ull m03 = kmax64(m01, m23);     int i03 = (m23 > m01) ? i23 : i01;
        ull m47 = kmax64(m45, m67);     int i47 = (m67 > m45) ? i67 : i45;
        ull best = kmax64(m03, m47);    int br  = (m47 > m03) ? i47 : i03;

        float nx, ny; upk2(xxy[buf][br], nx, ny);
        px = nx; py = ny; pz = xz[buf][br];
        if (rank == 0 && tid == 0) {                     // stash winner locally
            gidr[it + 1] = (int)((~(unsigned)best) & (N_ - 1));
            sxr[it + 1] = px; syr[it + 1] = py; szr[it + 1] = pz;
        }
    }
    cluster_sync_();          // no CTA exits while peers may still target its smem
    if (rank != 0) return;    // rank 0 runs stages 2-4 alone

    // ---------------- stages 2-4: 1024 -> 256 -> 64 -> 16 (local smem) -------
    float* ob = out + b * OUTW;
    int n = NPT1, offs = 0;
    const int cnts[3] = {256, 64, 16};
    __syncthreads();

    for (int st = 0; st < 3; ++st) {
        const int npt = cnts[st];
        for (int i = tid; i < n; i += TPB) sdist[i] = 1e10f;
        if (tid == 0) { sel[0] = 0; ob[offs] = (float)gidr[0]; }
        __syncthreads();
        float qx = sxr[0], qy = syr[0], qz = szr[0];

        for (int it = 0; it < npt - 1; ++it) {
            const int buf = it & 1;
            ull key = 0ull;
            for (int i = tid; i < n; i += TPB) {
                float d  = sqdist(sxr[i], syr[i], szr[i], qx, qy, qz);
                float nd = fminf(sdist[i], d);
                sdist[i] = nd;
                ull k = ((ull)__float_as_uint(nd) << 32) | (unsigned)~i;
                key = kmax64(key, k);
            }
#pragma unroll
            for (int o = 16; o; o >>= 1)
                key = kmax64(key, __shfl_xor_sync(0xffffffffu, key, o));
            if (lane == 0) wkey[buf][w] = key;
            __syncthreads();
            ull best = wkey[buf][0];
#pragma unroll
            for (int ww = 1; ww < TPB / 32; ww++) best = kmax64(best, wkey[buf][ww]);
            const int loc = (int)((~(unsigned)best) & (NPT1 - 1));
            if (tid == 0) {
                sel[it + 1] = loc;
                ob[offs + it + 1] = (float)gidr[loc];    // float32 output
            }
            qx = sxr[loc]; qy = syr[loc]; qz = szr[loc]; // broadcast LDS
        }
        __syncthreads();

        for (int i = tid; i < npt; i += TPB) {
            int s2 = sel[i];
            txr[i] = sxr[s2]; tyr[i] = syr[s2]; tzr[i] = szr[s2]; tgr[i] = gidr[s2];
        }
        __syncthreads();
        for (int i = tid; i < npt; i += TPB) {
            sxr[i] = txr[i]; syr[i] = tyr[i]; szr[i] = tzr[i]; gidr[i] = tgr[i];
        }
        __syncthreads();
        n = npt;
        offs += npt;   // 0 -> 256 -> 320
    }
}

// ---------------- launch ----------------
extern "C" void kernel_launch(void* const* d_in, const int* in_sizes, int n_in,
                              void* d_out, int out_size) {
    (void)in_sizes; (void)n_in; (void)out_size;
    const float* x = (const float*)d_in[0];
    float* out = (float*)d_out;

    cudaFuncSetAttribute(fps_fused,
                         cudaFuncAttributeMaxDynamicSharedMemorySize,
                         PPB * 3 * sizeof(float));

    fps_fused<<<B_ * NB, TPB, PPB * 3 * sizeof(float)>>>(x, out);
}

// round 14
// speedup vs baseline: 1.2628x; 1.0694x over previous
#include <cuda_runtime.h>
#include <cstdint>

#define B_    16
#define N_    131072
#define NB    8                   // CTAs per cluster = slices per batch
#define PPB   (N_ / NB)           // 16384 points per CTA
#define TPB   512
#define NQ    (PPB / (TPB * 4))   // 8 quads (32 points) per thread
#define NPT1  1024
#define OUTW  336                 // 256 + 64 + 16

typedef unsigned long long ull;

__device__ __forceinline__ ull kmax64(ull a, ull b) { return a > b ? a : b; }
__device__ __forceinline__ unsigned cluster_rank() {
    unsigned r; asm("mov.u32 %0, %%cluster_ctarank;" : "=r"(r)); return r;
}
__device__ __forceinline__ void cluster_sync_() {
    asm volatile("barrier.cluster.arrive.aligned;" ::: "memory");
    asm volatile("barrier.cluster.wait.aligned;" ::: "memory");
}
__device__ __forceinline__ uint32_t mapa_sh(uint32_t local_addr, unsigned rank) {
    uint32_t r;
    asm("mapa.shared::cluster.u32 %0, %1, %2;" : "=r"(r) : "r"(local_addr), "r"(rank));
    return r;
}
__device__ __forceinline__ void st_cluster_u64(uint32_t addr, ull v) {
    asm volatile("st.shared::cluster.b64 [%0], %1;" :: "r"(addr), "l"(v) : "memory");
}
__device__ __forceinline__ void st_cluster_u32(uint32_t addr, uint32_t v) {
    asm volatile("st.shared::cluster.b32 [%0], %1;" :: "r"(addr), "r"(v) : "memory");
}
__device__ __forceinline__ void mbar_arrive_rel_cluster(uint32_t mbar_addr) {
    asm volatile("mbarrier.arrive.release.cluster.shared::cluster.b64 _, [%0];"
                 :: "r"(mbar_addr) : "memory");
}
// HW-sleep wait (timeout hint) — matches the proven ptx_helpers pattern
__device__ __forceinline__ void mbar_wait_parity_cluster(uint32_t mbar, uint32_t parity) {
    asm volatile(
        "{\n\t"
        ".reg .pred P;\n\t"
        "W_%=:\n\t"
        "mbarrier.try_wait.parity.acquire.cluster.shared::cta.b64 P, [%0], %1, 0x989680;\n\t"
        "@!P bra W_%=;\n\t"
        "}" :: "r"(mbar), "r"(parity) : "memory");
}

// ---- packed f32x2 helpers (lanes bit-identical to scalar .rn ops) -----------
__device__ __forceinline__ ull pk2(float lo, float hi) {
    ull r; asm("mov.b64 %0, {%1, %2};" : "=l"(r) : "f"(lo), "f"(hi)); return r;
}
__device__ __forceinline__ void upk2(ull v, float& lo, float& hi) {
    asm("mov.b64 {%0, %1}, %2;" : "=f"(lo), "=f"(hi) : "l"(v));
}
__device__ __forceinline__ ull add2(ull a, ull b) {
    ull r; asm("add.rn.f32x2 %0, %1, %2;" : "=l"(r) : "l"(a), "l"(b)); return r;
}
__device__ __forceinline__ ull mul2(ull a, ull b) {
    ull r; asm("mul.rn.f32x2 %0, %1, %2;" : "=l"(r) : "l"(a), "l"(b)); return r;
}

// verified scalar form (rel_err 0.0): ((dx^2 + dy^2) + dz^2), no contraction
__device__ __forceinline__ float sqdist(float xx, float yy, float zz,
                                        float px, float py, float pz) {
    float dx = __fsub_rn(xx, px);
    float dy = __fsub_rn(yy, py);
    float dz = __fsub_rn(zz, pz);
    return __fadd_rn(__fadd_rn(__fmul_rn(dx, dx), __fmul_rn(dy, dy)),
                     __fmul_rn(dz, dz));
}

// warp argmax via 2x REDUX. REQUIRES m >= +0.0f in every participating lane
// (negative float bits would dominate the unsigned max).
__device__ __forceinline__ ull warp_key_reduce(float m, unsigned inv_idx) {
    const uint32_t dbits = __float_as_uint(m);
    const uint32_t dmax  = __reduce_max_sync(0xffffffffu, dbits);
    const uint32_t cand  = (dbits == dmax) ? inv_idx : 0u;
    const uint32_t imax  = __reduce_max_sync(0xffffffffu, cand);
    return ((ull)dmax << 32) | imax;
}

// ======================= single fused kernel =================================
__global__ void __launch_bounds__(TPB, 1) __cluster_dims__(NB, 1, 1)
fps_fused(const float* __restrict__ x, float* __restrict__ out) {
    const unsigned rank = cluster_rank();
    const int b = blockIdx.x / NB;
    extern __shared__ float smemf[];            // SoA: x | y | z (192 KB)
    float* sxx = smemf;
    float* syy = smemf + PPB;
    float* szz = smemf + 2 * PPB;

    __shared__ __align__(16) ull xkey[2][NB];   // exchanged keys
    __shared__ ull xxy[2][NB];                  // exchanged (x,y) packed
    __shared__ float xz[2][NB];                 // exchanged z
    __shared__ __align__(16) ull wkey[2][TPB / 32];
    __shared__ ull mbar;
    // rank-0 epilogue arrays (~26 KB static)
    __shared__ float sxr[NPT1], syr[NPT1], szr[NPT1], sdist[NPT1];
    __shared__ int   gidr[NPT1];
    __shared__ int   sel[256];
    __shared__ float txr[256], tyr[256], tzr[256];
    __shared__ int   tgr[256];

    const float* xb = x + (size_t)b * (N_ * 3);
    const int base = (int)rank * PPB;
    const int tid = threadIdx.x;
    const int lane = tid & 31;
    const int w    = tid >> 5;

    // AoS global -> SoA smem
    for (int i = tid; i < PPB; i += TPB) {
        const float* p = xb + (size_t)(base + i) * 3;
        sxx[i] = p[0]; syy[i] = p[1]; szz[i] = p[2];
    }
    if (tid == 0) {
        asm volatile("mbarrier.init.shared.b64 [%0], %1;"
                     :: "r"((uint32_t)__cvta_generic_to_shared(&mbar)), "r"(NB)
                     : "memory");
    }
    __syncthreads();
    cluster_sync_();   // all mbarriers live before any remote arrive

    float dist[4 * NQ];
#pragma unroll
    for (int j = 0; j < 4 * NQ; j++) dist[j] = 1e10f;

    // first sampled point: global index 0
    float px = xb[0], py = xb[1], pz = xb[2];
    if (rank == 0 && tid == 0) {
        gidr[0] = 0; sxr[0] = px; syr[0] = py; szr[0] = pz;
    }

    const int t4 = tid * 4;
    const uint32_t mbar_lcl = (uint32_t)__cvta_generic_to_shared(&mbar);

    for (int it = 0; it < NPT1 - 1; ++it) {
        const int buf = it & 1;
        const ull npx2 = pk2(-px, -px);
        const ull npy2 = pk2(-py, -py);
        const ull npz2 = pk2(-pz, -pz);

        // ---- distance update: packed pairs straight from LDS.128 ------------
#pragma unroll
        for (int q = 0; q < NQ; ++q) {
            const int lp = q * (TPB * 4) + t4;          // 4 consecutive points
            ulonglong2 xq = *(const ulonglong2*)(sxx + lp);
            ulonglong2 yq = *(const ulonglong2*)(syy + lp);
            ulonglong2 zq = *(const ulonglong2*)(szz + lp);
            ull dxa = add2(xq.x, npx2), dxb = add2(xq.y, npx2);
            ull dya = add2(yq.x, npy2), dyb = add2(yq.y, npy2);
            ull dza = add2(zq.x, npz2), dzb = add2(zq.y, npz2);
            ull ssa = add2(add2(mul2(dxa, dxa), mul2(dya, dya)), mul2(dza, dza));
            ull ssb = add2(add2(mul2(dxb, dxb), mul2(dyb, dyb)), mul2(dzb, dzb));
            float d0, d1, d2, d3;
            upk2(ssa, d0, d1);
            upk2(ssb, d2, d3);
            const int k = q * 4;
            dist[k + 0] = fminf(dist[k + 0], d0);
            dist[k + 1] = fminf(dist[k + 1], d1);
            dist[k + 2] = fminf(dist[k + 2], d2);
            dist[k + 3] = fminf(dist[k + 3], d3);
        }
        // ---- max via tree (depth 5, parallel) -------------------------------
        float t16[16];
#pragma unroll
        for (int k = 0; k < 16; ++k) t16[k] = fmaxf(dist[2 * k], dist[2 * k + 1]);
        float t8[8];
#pragma unroll
        for (int k = 0; k < 8; ++k) t8[k] = fmaxf(t16[2 * k], t16[2 * k + 1]);
        float ta = fmaxf(fmaxf(t8[0], t8[1]), fmaxf(t8[2], t8[3]));
        float tb = fmaxf(fmaxf(t8[4], t8[5]), fmaxf(t8[6], t8[7]));
        float m = fmaxf(ta, tb);
        // ---- first (smallest-k) element equal to m --------------------------
        int kk = 0;
#pragma unroll
        for (int k = 4 * NQ - 1; k >= 0; --k)
            if (dist[k] == m) kk = k;                   // last write = smallest k
        const int e_win = (kk >> 2) * (TPB * 4) + t4 + (kk & 3);

        // ---- warp argmax via REDUX (m >= 0 here: all lanes active) ----------
        ull key = warp_key_reduce(m, (unsigned)~(base + e_win));
        if (lane == 0) wkey[buf][w] = key;
        __syncthreads();                                 // only block bar / iter

        if (w == 0) {                                    // 16 warp keys -> best
            ull k2 = (lane < TPB / 32) ? wkey[buf][lane] : 0ull;
            const uint32_t hi = (uint32_t)(k2 >> 32), lo = (uint32_t)k2;
            const uint32_t hmax = __reduce_max_sync(0xffffffffu, hi);
            const uint32_t lmax = __reduce_max_sync(0xffffffffu, (hi == hmax) ? lo : 0u);
            k2 = ((ull)hmax << 32) | lmax;
            const int loc = (int)((~(unsigned)k2) & (N_ - 1)) - base;
            const float wxv = sxx[loc], wyv = syy[loc], wzv = szz[loc];
            if (lane < NB) {
                const uint32_t ka = mapa_sh((uint32_t)__cvta_generic_to_shared(&xkey[buf][rank]), (unsigned)lane);
                const uint32_t ca = mapa_sh((uint32_t)__cvta_generic_to_shared(&xxy[buf][rank]),  (unsigned)lane);
                const uint32_t za = mapa_sh((uint32_t)__cvta_generic_to_shared(&xz[buf][rank]),   (unsigned)lane);
                st_cluster_u64(ka, k2);
                st_cluster_u64(ca, pk2(wxv, wyv));
                st_cluster_u32(za, __float_as_uint(wzv));
                mbar_arrive_rel_cluster(mapa_sh(mbar_lcl, (unsigned)lane));
            }
        }
        mbar_wait_parity_cluster(mbar_lcl, (uint32_t)buf);

        // ---- reduce 8 exchanged keys: LDS.128 x4 + depth-3 tree -------------
        const ulonglong2* xk = (const ulonglong2*)&xkey[buf][0];
        ulonglong2 p01 = xk[0], p23 = xk[1], p45 = xk[2], p67 = xk[3];
        ull m01 = kmax64(p01.x, p01.y); int i01 = (p01.y > p01.x) ? 1 : 0;
        ull m23 = kmax64(p23.x, p23.y); int i23 = (p23.y > p23.x) ? 3 : 2;
        ull m45 = kmax64(p45.x, p45.y); int i45 = (p45.y > p45.x) ? 5 : 4;
        ull m67 = kmax64(p67.x, p67.y); int i67 = (p67.y > p67.x) ? 7 : 6;
        ull m03 = kmax64(m01, m23);     int i03 = (m23 > m01) ? i23 : i01;
        ull m47 = kmax64(m45, m67);     int i47 = (m67 > m45) ? i67 : i45;
        ull best = kmax64(m03, m47);    int br  = (m47 > m03) ? i47 : i03;

        float nx, ny; upk2(xxy[buf][br], nx, ny);
        px = nx; py = ny; pz = xz[buf][br];
        if (rank == 0 && tid == 0) {                     // stash winner locally
            gidr[it + 1] = (int)((~(unsigned)best) & (N_ - 1));
            sxr[it + 1] = px; syr[it + 1] = py; szr[it + 1] = pz;
        }
    }
    cluster_sync_();          // no CTA exits while peers may still target its smem
    if (rank != 0) return;    // rank 0 runs stages 2-4 alone

    // ---------------- stages 2-4: 1024 -> 256 -> 64 -> 16 (local smem) -------
    float* ob = out + b * OUTW;
    int n = NPT1, offs = 0;
    const int cnts[3] = {256, 64, 16};
    __syncthreads();

    for (int st = 0; st < 3; ++st) {
        const int npt = cnts[st];
        for (int i = tid; i < n; i += TPB) sdist[i] = 1e10f;
        if (tid == 0) { sel[0] = 0; ob[offs] = (float)gidr[0]; }
        __syncthreads();
        float qx = sxr[0], qy = syr[0], qz = szr[0];

        for (int it = 0; it < npt - 1; ++it) {
            const int buf = it & 1;
            // FIX R13: init with +0.0f (NOT -1.0f). Idle threads (tid >= n)
            // contribute 0-bits which can never beat a real positive max.
            float bm = 0.0f; unsigned binv = 0u;
            for (int i = tid; i < n; i += TPB) {
                float d  = sqdist(sxr[i], syr[i], szr[i], qx, qy, qz);
                float nd = fminf(sdist[i], d);
                sdist[i] = nd;
                if (nd > bm) { bm = nd; binv = (unsigned)~i; }
                else if (nd == bm) { binv = binv > (unsigned)~i ? binv : (unsigned)~i; }
            }
            ull key = warp_key_reduce(bm, binv);
            if (lane == 0) wkey[buf][w] = key;
            __syncthreads();
            ull best = wkey[buf][0];
#pragma unroll
            for (int ww = 1; ww < TPB / 32; ww++) best = kmax64(best, wkey[buf][ww]);
            const int loc = (int)((~(unsigned)best) & (NPT1 - 1));
            if (tid == 0) {
                sel[it + 1] = loc;
                ob[offs + it + 1] = (float)gidr[loc];    // float32 output
            }
            qx = sxr[loc]; qy = syr[loc]; qz = szr[loc]; // broadcast LDS
        }
        __syncthreads();

        for (int i = tid; i < npt; i += TPB) {
            int s2 = sel[i];
            txr[i] = sxr[s2]; tyr[i] = syr[s2]; tzr[i] = szr[s2]; tgr[i] = gidr[s2];
        }
        __syncthreads();
        for (int i = tid; i < npt; i += TPB) {
            sxr[i] = txr[i]; syr[i] = tyr[i]; szr[i] = tzr[i]; gidr[i] = tgr[i];
        }
        __syncthreads();
        n = npt;
        offs += npt;   // 0 -> 256 -> 320
    }
}

// ---------------- launch ----------------
extern "C" void kernel_launch(void* const* d_in, const int* in_sizes, int n_in,
                              void* d_out, int out_size) {
    (void)in_sizes; (void)n_in; (void)out_size;
    const float* x = (const float*)d_in[0];
    float* out = (float*)d_out;

    cudaFuncSetAttribute(fps_fused,
                         cudaFuncAttributeMaxDynamicSharedMemorySize,
                         PPB * 3 * sizeof(float));

    fps_fused<<<B_ * NB, TPB, PPB * 3 * sizeof(float)>>>(x, out);
}

// round 15
// speedup vs baseline: 1.3266x; 1.0505x over previous
#include <cuda_runtime.h>
#include <cstdint>

#define B_    16
#define N_    131072
#define NB    8                   // CTAs per cluster = slices per batch
#define PPB   (N_ / NB)           // 16384 points per CTA
#define TPB   512
#define NQ    (PPB / (TPB * 4))   // 8 quads (32 points) per thread
#define NPT1  1024
#define OUTW  336                 // 256 + 64 + 16

typedef unsigned long long ull;

// stage-1 winner keys, plain-stored by cluster rank 0 each iteration
__device__ ull g_key[B_][NPT1];

__device__ __forceinline__ ull kmax64(ull a, ull b) { return a > b ? a : b; }
__device__ __forceinline__ unsigned cluster_rank() {
    unsigned r; asm("mov.u32 %0, %%cluster_ctarank;" : "=r"(r)); return r;
}
__device__ __forceinline__ void cluster_sync_() {
    asm volatile("barrier.cluster.arrive.aligned;" ::: "memory");
    asm volatile("barrier.cluster.wait.aligned;" ::: "memory");
}
__device__ __forceinline__ uint32_t mapa_sh(uint32_t local_addr, unsigned rank) {
    uint32_t r;
    asm("mapa.shared::cluster.u32 %0, %1, %2;" : "=r"(r) : "r"(local_addr), "r"(rank));
    return r;
}
__device__ __forceinline__ void st_cluster_u64(uint32_t addr, ull v) {
    asm volatile("st.shared::cluster.b64 [%0], %1;" :: "r"(addr), "l"(v) : "memory");
}
__device__ __forceinline__ void st_cluster_u32(uint32_t addr, uint32_t v) {
    asm volatile("st.shared::cluster.b32 [%0], %1;" :: "r"(addr), "r"(v) : "memory");
}
__device__ __forceinline__ void mbar_arrive_rel_cluster(uint32_t mbar_addr) {
    asm volatile("mbarrier.arrive.release.cluster.shared::cluster.b64 _, [%0];"
                 :: "r"(mbar_addr) : "memory");
}
// R10-proven hot-spin wait (no sleep hint)
__device__ __forceinline__ void mbar_wait_parity_cluster(uint32_t mbar, uint32_t parity) {
    asm volatile(
        "{\n\t"
        ".reg .pred P;\n\t"
        "W_%=:\n\t"
        "mbarrier.try_wait.parity.acquire.cluster.shared::cta.b64 P, [%0], %1;\n\t"
        "@!P bra W_%=;\n\t"
        "}" :: "r"(mbar), "r"(parity) : "memory");
}

// ---- packed f32x2 helpers (lanes bit-identical to scalar .rn ops) -----------
__device__ __forceinline__ ull pk2(float lo, float hi) {
    ull r; asm("mov.b64 %0, {%1, %2};" : "=l"(r) : "f"(lo), "f"(hi)); return r;
}
__device__ __forceinline__ void upk2(ull v, float& lo, float& hi) {
    asm("mov.b64 {%0, %1}, %2;" : "=f"(lo), "=f"(hi) : "l"(v));
}
__device__ __forceinline__ ull add2(ull a, ull b) {
    ull r; asm("add.rn.f32x2 %0, %1, %2;" : "=l"(r) : "l"(a), "l"(b)); return r;
}
__device__ __forceinline__ ull mul2(ull a, ull b) {
    ull r; asm("mul.rn.f32x2 %0, %1, %2;" : "=l"(r) : "l"(a), "l"(b)); return r;
}

// verified scalar form (rel_err 0.0): ((dx^2 + dy^2) + dz^2), no contraction
__device__ __forceinline__ float sqdist(float xx, float yy, float zz,
                                        float px, float py, float pz) {
    float dx = __fsub_rn(xx, px);
    float dy = __fsub_rn(yy, py);
    float dz = __fsub_rn(zz, pz);
    return __fadd_rn(__fadd_rn(__fmul_rn(dx, dx), __fmul_rn(dy, dy)),
                     __fmul_rn(dz, dz));
}

// ---------------- stage 1: 131072 -> 1024, one 8-CTA cluster per batch -------
__global__ void __launch_bounds__(TPB, 1) __cluster_dims__(NB, 1, 1)
fps_stage1(const float* __restrict__ x) {
    const unsigned rank = cluster_rank();
    const int b = blockIdx.x / NB;
    extern __shared__ float smemf[];            // SoA: x | y | z (192 KB)
    float* sxx = smemf;
    float* syy = smemf + PPB;
    float* szz = smemf + 2 * PPB;

    __shared__ __align__(16) ull xkey[2][NB];   // exchanged keys
    __shared__ ull xxy[2][NB];                  // exchanged (x,y) packed
    __shared__ float xz[2][NB];                 // exchanged z
    __shared__ ull wkey[2][TPB / 32];
    __shared__ ull mbar;

    const float* xb = x + (size_t)b * (N_ * 3);
    const int base = (int)rank * PPB;
    const int tid = threadIdx.x;
    const int lane = tid & 31;
    const int w    = tid >> 5;

    // AoS global -> SoA smem
    for (int i = tid; i < PPB; i += TPB) {
        const float* p = xb + (size_t)(base + i) * 3;
        sxx[i] = p[0]; syy[i] = p[1]; szz[i] = p[2];
    }
    if (tid == 0) {
        asm volatile("mbarrier.init.shared.b64 [%0], %1;"
                     :: "r"((uint32_t)__cvta_generic_to_shared(&mbar)), "r"(NB)
                     : "memory");
    }
    __syncthreads();
    cluster_sync_();   // all mbarriers live before any remote arrive

    float dist[4 * NQ];
#pragma unroll
    for (int j = 0; j < 4 * NQ; j++) dist[j] = 1e10f;

    // first sampled point: global index 0
    float px = xb[0], py = xb[1], pz = xb[2];

    const int t4 = tid * 4;
    const uint32_t mbar_lcl = (uint32_t)__cvta_generic_to_shared(&mbar);

    // prefetch quad 0 for the first iteration (coords are loop-invariant)
    ulonglong2 pfx = *(const ulonglong2*)(sxx + t4);
    ulonglong2 pfy = *(const ulonglong2*)(syy + t4);
    ulonglong2 pfz = *(const ulonglong2*)(szz + t4);

    for (int it = 0; it < NPT1 - 1; ++it) {
        const int buf = it & 1;
        const ull npx2 = pk2(-px, -px);
        const ull npy2 = pk2(-py, -py);
        const ull npz2 = pk2(-pz, -pz);

        float m = -1.0f;
        int   mi = 0;
#pragma unroll
        for (int q = 0; q < NQ; ++q) {
            const int lp = q * (TPB * 4) + t4;          // 4 consecutive points
            ulonglong2 xq, yq, zq;
            if (q == 0) { xq = pfx; yq = pfy; zq = pfz; }
            else {
                xq = *(const ulonglong2*)(sxx + lp);
                yq = *(const ulonglong2*)(syy + lp);
                zq = *(const ulonglong2*)(szz + lp);
            }
            ull dxa = add2(xq.x, npx2), dxb = add2(xq.y, npx2);
            ull dya = add2(yq.x, npy2), dyb = add2(yq.y, npy2);
            ull dza = add2(zq.x, npz2), dzb = add2(zq.y, npz2);
            ull ssa = add2(add2(mul2(dxa, dxa), mul2(dya, dya)), mul2(dza, dza));
            ull ssb = add2(add2(mul2(dxb, dxb), mul2(dyb, dyb)), mul2(dzb, dzb));
            float d0, d1, d2, d3;
            upk2(ssa, d0, d1);
            upk2(ssb, d2, d3);
            const int k = q * 4;
            float nd;
            nd = fminf(dist[k + 0], d0); dist[k + 0] = nd; if (nd > m) { m = nd; mi = lp + 0; }
            nd = fminf(dist[k + 1], d1); dist[k + 1] = nd; if (nd > m) { m = nd; mi = lp + 1; }
            nd = fminf(dist[k + 2], d2); dist[k + 2] = nd; if (nd > m) { m = nd; mi = lp + 2; }
            nd = fminf(dist[k + 3], d3); dist[k + 3] = nd; if (nd > m) { m = nd; mi = lp + 3; }
        }
        // key: (dist_bits<<32) | ~idx ; dist>=0 -> bits monotone; ties -> min idx
        ull key = ((ull)__float_as_uint(m) << 32) | (unsigned)~(base + mi);
#pragma unroll
        for (int o = 16; o; o >>= 1)
            key = kmax64(key, __shfl_xor_sync(0xffffffffu, key, o));
        if (lane == 0) wkey[buf][w] = key;
        __syncthreads();                                 // only block bar / iter

        if (w == 0) {                                    // 16 warp keys -> best
            ull k2 = wkey[buf][lane & 15];
#pragma unroll
            for (int o = 8; o; o >>= 1)
                k2 = kmax64(k2, __shfl_xor_sync(0xffffffffu, k2, o));
            const int loc = (int)((~(unsigned)k2) & (N_ - 1)) - base;
            const float wxv = sxx[loc], wyv = syy[loc], wzv = szz[loc];
            if (lane < NB) {
                const uint32_t ka = mapa_sh((uint32_t)__cvta_generic_to_shared(&xkey[buf][rank]), (unsigned)lane);
                const uint32_t ca = mapa_sh((uint32_t)__cvta_generic_to_shared(&xxy[buf][rank]),  (unsigned)lane);
                const uint32_t za = mapa_sh((uint32_t)__cvta_generic_to_shared(&xz[buf][rank]),   (unsigned)lane);
                st_cluster_u64(ka, k2);
                st_cluster_u64(ca, pk2(wxv, wyv));
                st_cluster_u32(za, __float_as_uint(wzv));
                mbar_arrive_rel_cluster(mapa_sh(mbar_lcl, (unsigned)lane));
            }
        }
        // prefetch quad 0 for NEXT iteration while the exchange is in flight
        pfx = *(const ulonglong2*)(sxx + t4);
        pfy = *(const ulonglong2*)(syy + t4);
        pfz = *(const ulonglong2*)(szz + t4);

        mbar_wait_parity_cluster(mbar_lcl, (uint32_t)buf);

        // every thread reduces the 8 cluster keys (R10-proven serial-8)
        ull best = xkey[buf][0];
        int br = 0;
#pragma unroll
        for (int k = 1; k < NB; k++) {
            ull v = xkey[buf][k];
            if (v > best) { best = v; br = k; }
        }
        if (rank == 0 && tid == 0) g_key[b][it] = best;   // plain store
        float nx, ny; upk2(xxy[buf][br], nx, ny);
        px = nx; py = ny; pz = xz[buf][br];
    }
    cluster_sync_();   // no CTA exits while peers may still target its smem
}

// ---------------- stages 2-4: 1024 -> 256 -> 64 -> 16 (one block per batch) ---
#define RT 256
__global__ void __launch_bounds__(RT, 1)
fps_rest(const float* __restrict__ x, float* __restrict__ out) {
    const int b = blockIdx.x;
    __shared__ float sx[NPT1], sy[NPT1], sz[NPT1], sdist[NPT1];
    __shared__ int   gid[NPT1];
    __shared__ int   sel[256];
    __shared__ float tx[256], ty[256], tz[256];
    __shared__ int   tg[256];
    __shared__ ull wkey[2][RT / 32];

    const float* xb = x + (size_t)b * (N_ * 3);
    float* ob = out + b * OUTW;
    const int tid = threadIdx.x;
    const int lane = tid & 31, w = tid >> 5;

    // decode stage-1 winners (index 0 is the implicit first sample)
    for (int i = tid; i < NPT1; i += RT) {
        unsigned idx = (i == 0) ? 0u : ((~(unsigned)g_key[b][i - 1]) & (N_ - 1));
        gid[i] = (int)idx;
        sx[i] = xb[(size_t)idx * 3 + 0];
        sy[i] = xb[(size_t)idx * 3 + 1];
        sz[i] = xb[(size_t)idx * 3 + 2];
    }
    __syncthreads();

    int n = NPT1, offs = 0;
    const int cnts[3] = {256, 64, 16};

    for (int st = 0; st < 3; ++st) {
        const int npt = cnts[st];
        for (int i = tid; i < n; i += RT) sdist[i] = 1e10f;
        if (tid == 0) { sel[0] = 0; ob[offs] = (float)gid[0]; }
        __syncthreads();
        float px = sx[0], py = sy[0], pz = sz[0];

        for (int it = 0; it < npt - 1; ++it) {
            const int buf = it & 1;
            ull key = 0ull;
            for (int i = tid; i < n; i += RT) {
                float d  = sqdist(sx[i], sy[i], sz[i], px, py, pz);
                float nd = fminf(sdist[i], d);
                sdist[i] = nd;
                ull k = ((ull)__float_as_uint(nd) << 32) | (unsigned)~i;
                key = kmax64(key, k);
            }
#pragma unroll
            for (int o = 16; o; o >>= 1)
                key = kmax64(key, __shfl_xor_sync(0xffffffffu, key, o));
            if (lane == 0) wkey[buf][w] = key;
            __syncthreads();                               // only bar per iter
            ull best = wkey[buf][0];
#pragma unroll
            for (int ww = 1; ww < RT / 32; ww++) best = kmax64(best, wkey[buf][ww]);
            const int loc = (int)((~(unsigned)best) & (NPT1 - 1));
            if (tid == 0) {
                sel[it + 1] = loc;
                ob[offs + it + 1] = (float)gid[loc];       // float32 output
            }
            px = sx[loc]; py = sy[loc]; pz = sz[loc];      // broadcast LDS
        }
        __syncthreads();                                   // sel[] ready

        // compact the selected npt points to the front for the next stage
        for (int i = tid; i < npt; i += RT) {
            int s2 = sel[i];
            tx[i] = sx[s2]; ty[i] = sy[s2]; tz[i] = sz[s2]; tg[i] = gid[s2];
        }
        __syncthreads();
        for (int i = tid; i < npt; i += RT) {
            sx[i] = tx[i]; sy[i] = ty[i]; sz[i] = tz[i]; gid[i] = tg[i];
        }
        __syncthreads();
        n = npt;
        offs += npt;   // 0 -> 256 -> 320
    }
}

// ---------------- launch ----------------
extern "C" void kernel_launch(void* const* d_in, const int* in_sizes, int n_in,
                              void* d_out, int out_size) {
    (void)in_sizes; (void)n_in; (void)out_size;
    const float* x = (const float*)d_in[0];
    float* out = (float*)d_out;

    cudaFuncSetAttribute(fps_stage1,
                         cudaFuncAttributeMaxDynamicSharedMemorySize,
                         PPB * 3 * sizeof(float));

    fps_stage1<<<B_ * NB, TPB, PPB * 3 * sizeof(float)>>>(x);
    fps_rest<<<B_, RT>>>(x, out);
}

// round 16
// speedup vs baseline: 1.3623x; 1.0270x over previous
#include <cuda_runtime.h>
#include <cstdint>

#define B_    16
#define N_    131072
#define NB    8                   // CTAs per cluster = slices per batch
#define PPB   (N_ / NB)           // 16384 points per CTA
#define TPB   512
#define NQ    (PPB / (TPB * 4))   // 8 quads (32 points) per thread
#define NPT1  1024
#define OUTW  336                 // 256 + 64 + 16

typedef unsigned long long ull;

// stage-1 winner keys, plain-stored by cluster rank 0 each iteration
__device__ ull g_key[B_][NPT1];

__device__ __forceinline__ ull kmax64(ull a, ull b) { return a > b ? a : b; }
__device__ __forceinline__ unsigned cluster_rank() {
    unsigned r; asm("mov.u32 %0, %%cluster_ctarank;" : "=r"(r)); return r;
}
__device__ __forceinline__ void cluster_sync_() {
    asm volatile("barrier.cluster.arrive.aligned;" ::: "memory");
    asm volatile("barrier.cluster.wait.aligned;" ::: "memory");
}
__device__ __forceinline__ uint32_t mapa_sh(uint32_t local_addr, unsigned rank) {
    uint32_t r;
    asm("mapa.shared::cluster.u32 %0, %1, %2;" : "=r"(r) : "r"(local_addr), "r"(rank));
    return r;
}
__device__ __forceinline__ void st_cluster_u64(uint32_t addr, ull v) {
    asm volatile("st.shared::cluster.b64 [%0], %1;" :: "r"(addr), "l"(v) : "memory");
}
__device__ __forceinline__ void st_cluster_u32(uint32_t addr, uint32_t v) {
    asm volatile("st.shared::cluster.b32 [%0], %1;" :: "r"(addr), "r"(v) : "memory");
}
__device__ __forceinline__ void mbar_arrive_rel_cluster(uint32_t mbar_addr) {
    asm volatile("mbarrier.arrive.release.cluster.shared::cluster.b64 _, [%0];"
                 :: "r"(mbar_addr) : "memory");
}
// hot-spin wait — now executed by ONE warp per CTA only
__device__ __forceinline__ void mbar_wait_parity_cluster(uint32_t mbar, uint32_t parity) {
    asm volatile(
        "{\n\t"
        ".reg .pred P;\n\t"
        "W_%=:\n\t"
        "mbarrier.try_wait.parity.acquire.cluster.shared::cta.b64 P, [%0], %1;\n\t"
        "@!P bra W_%=;\n\t"
        "}" :: "r"(mbar), "r"(parity) : "memory");
}

// ---- packed f32x2 helpers (lanes bit-identical to scalar .rn ops) -----------
__device__ __forceinline__ ull pk2(float lo, float hi) {
    ull r; asm("mov.b64 %0, {%1, %2};" : "=l"(r) : "f"(lo), "f"(hi)); return r;
}
__device__ __forceinline__ void upk2(ull v, float& lo, float& hi) {
    asm("mov.b64 {%0, %1}, %2;" : "=f"(lo), "=f"(hi) : "l"(v));
}
__device__ __forceinline__ ull add2(ull a, ull b) {
    ull r; asm("add.rn.f32x2 %0, %1, %2;" : "=l"(r) : "l"(a), "l"(b)); return r;
}
__device__ __forceinline__ ull mul2(ull a, ull b) {
    ull r; asm("mul.rn.f32x2 %0, %1, %2;" : "=l"(r) : "l"(a), "l"(b)); return r;
}

// verified scalar form (rel_err 0.0): ((dx^2 + dy^2) + dz^2), no contraction
__device__ __forceinline__ float sqdist(float xx, float yy, float zz,
                                        float px, float py, float pz) {
    float dx = __fsub_rn(xx, px);
    float dy = __fsub_rn(yy, py);
    float dz = __fsub_rn(zz, pz);
    return __fadd_rn(__fadd_rn(__fmul_rn(dx, dx), __fmul_rn(dy, dy)),
                     __fmul_rn(dz, dz));
}

// ---------------- stage 1: 131072 -> 1024, one 8-CTA cluster per batch -------
__global__ void __launch_bounds__(TPB, 1) __cluster_dims__(NB, 1, 1)
fps_stage1(const float* __restrict__ x) {
    const unsigned rank = cluster_rank();
    const int b = blockIdx.x / NB;
    extern __shared__ float smemf[];            // SoA: x | y | z (192 KB)
    float* sxx = smemf;
    float* syy = smemf + PPB;
    float* szz = smemf + 2 * PPB;

    __shared__ __align__(16) ull xkey[2][NB];   // exchanged keys
    __shared__ ull xxy[2][NB];                  // exchanged (x,y) packed
    __shared__ float xz[2][NB];                 // exchanged z
    __shared__ ull wkey[TPB / 32];
    __shared__ ull spiv_xy;                     // published pivot (x,y)
    __shared__ float spiv_z;                    // published pivot z
    __shared__ ull sbest;                       // published winning key
    __shared__ ull mbar;

    const float* xb = x + (size_t)b * (N_ * 3);
    const int base = (int)rank * PPB;
    const int tid = threadIdx.x;
    const int lane = tid & 31;
    const int w    = tid >> 5;

    // AoS global -> SoA smem
    for (int i = tid; i < PPB; i += TPB) {
        const float* p = xb + (size_t)(base + i) * 3;
        sxx[i] = p[0]; syy[i] = p[1]; szz[i] = p[2];
    }
    if (tid == 0) {
        asm volatile("mbarrier.init.shared.b64 [%0], %1;"
                     :: "r"((uint32_t)__cvta_generic_to_shared(&mbar)), "r"(NB)
                     : "memory");
    }
    __syncthreads();
    cluster_sync_();   // all mbarriers live before any remote arrive

    float dist[4 * NQ];
#pragma unroll
    for (int j = 0; j < 4 * NQ; j++) dist[j] = 1e10f;

    // first sampled point: global index 0
    float px = xb[0], py = xb[1], pz = xb[2];
    if (rank == 0 && tid == 0) g_key[b][NPT1 - 1] = 0ull;  // unused slot; keep clean

    const int t4 = tid * 4;
    const uint32_t mbar_lcl = (uint32_t)__cvta_generic_to_shared(&mbar);

    // prefetch quad 0 for the first iteration (coords are loop-invariant)
    ulonglong2 pfx = *(const ulonglong2*)(sxx + t4);
    ulonglong2 pfy = *(const ulonglong2*)(syy + t4);
    ulonglong2 pfz = *(const ulonglong2*)(szz + t4);

    for (int it = 0; it < NPT1 - 1; ++it) {
        const int buf = it & 1;
        const ull npx2 = pk2(-px, -px);
        const ull npy2 = pk2(-py, -py);
        const ull npz2 = pk2(-pz, -pz);

        float m = -1.0f;
        int   mi = 0;
#pragma unroll
        for (int q = 0; q < NQ; ++q) {
            const int lp = q * (TPB * 4) + t4;          // 4 consecutive points
            ulonglong2 xq, yq, zq;
            if (q == 0) { xq = pfx; yq = pfy; zq = pfz; }
            else {
                xq = *(const ulonglong2*)(sxx + lp);
                yq = *(const ulonglong2*)(syy + lp);
                zq = *(const ulonglong2*)(szz + lp);
            }
            ull dxa = add2(xq.x, npx2), dxb = add2(xq.y, npx2);
            ull dya = add2(yq.x, npy2), dyb = add2(yq.y, npy2);
            ull dza = add2(zq.x, npz2), dzb = add2(zq.y, npz2);
            ull ssa = add2(add2(mul2(dxa, dxa), mul2(dya, dya)), mul2(dza, dza));
            ull ssb = add2(add2(mul2(dxb, dxb), mul2(dyb, dyb)), mul2(dzb, dzb));
            float d0, d1, d2, d3;
            upk2(ssa, d0, d1);
            upk2(ssb, d2, d3);
            const int k = q * 4;
            float nd;
            nd = fminf(dist[k + 0], d0); dist[k + 0] = nd; if (nd > m) { m = nd; mi = lp + 0; }
            nd = fminf(dist[k + 1], d1); dist[k + 1] = nd; if (nd > m) { m = nd; mi = lp + 1; }
            nd = fminf(dist[k + 2], d2); dist[k + 2] = nd; if (nd > m) { m = nd; mi = lp + 2; }
            nd = fminf(dist[k + 3], d3); dist[k + 3] = nd; if (nd > m) { m = nd; mi = lp + 3; }
        }
        // key: (dist_bits<<32) | ~idx ; dist>=0 -> bits monotone; ties -> min idx
        ull key = ((ull)__float_as_uint(m) << 32) | (unsigned)~(base + mi);
#pragma unroll
        for (int o = 16; o; o >>= 1)
            key = kmax64(key, __shfl_xor_sync(0xffffffffu, key, o));
        if (lane == 0) wkey[w] = key;
        __syncthreads();                                 // bar1: wkey ready

        // all warps: prefetch quad 0 for next iteration (address loop-invariant)
        pfx = *(const ulonglong2*)(sxx + t4);
        pfy = *(const ulonglong2*)(syy + t4);
        pfz = *(const ulonglong2*)(szz + t4);

        if (w == 0) {   // WARP 0 ONLY: reduce, exchange, wait, publish
            ull k2 = wkey[lane & 15];
#pragma unroll
            for (int o = 8; o; o >>= 1)
                k2 = kmax64(k2, __shfl_xor_sync(0xffffffffu, k2, o));
            const int loc = (int)((~(unsigned)k2) & (N_ - 1)) - base;
            const float wxv = sxx[loc], wyv = syy[loc], wzv = szz[loc];
            if (lane < NB) {
                const uint32_t ka = mapa_sh((uint32_t)__cvta_generic_to_shared(&xkey[buf][rank]), (unsigned)lane);
                const uint32_t ca = mapa_sh((uint32_t)__cvta_generic_to_shared(&xxy[buf][rank]),  (unsigned)lane);
                const uint32_t za = mapa_sh((uint32_t)__cvta_generic_to_shared(&xz[buf][rank]),   (unsigned)lane);
                st_cluster_u64(ka, k2);
                st_cluster_u64(ca, pk2(wxv, wyv));
                st_cluster_u32(za, __float_as_uint(wzv));
                mbar_arrive_rel_cluster(mapa_sh(mbar_lcl, (unsigned)lane));
            }
            mbar_wait_parity_cluster(mbar_lcl, (uint32_t)buf);   // single waiter

            if (lane == 0) {   // reduce 8 exchanged keys once, publish pivot
                ull best = xkey[buf][0];
                int br = 0;
#pragma unroll
                for (int k = 1; k < NB; k++) {
                    ull v = xkey[buf][k];
                    if (v > best) { best = v; br = k; }
                }
                spiv_xy = xxy[buf][br];
                spiv_z  = xz[buf][br];
                sbest   = best;
            }
        }
        __syncthreads();                                 // bar2: pivot published

        float nx, ny; upk2(spiv_xy, nx, ny);
        px = nx; py = ny; pz = spiv_z;
        if (rank == 0 && tid == 0) g_key[b][it] = sbest; // plain store
    }
    cluster_sync_();   // no CTA exits while peers may still target its smem
}

// ---------------- stages 2-4: 1024 -> 256 -> 64 -> 16 (one block per batch) ---
#define RT 256
__global__ void __launch_bounds__(RT, 1)
fps_rest(const float* __restrict__ x, float* __restrict__ out) {
    const int b = blockIdx.x;
    __shared__ float sx[NPT1], sy[NPT1], sz[NPT1], sdist[NPT1];
    __shared__ int   gid[NPT1];
    __shared__ int   sel[256];
    __shared__ float tx[256], ty[256], tz[256];
    __shared__ int   tg[256];
    __shared__ ull wkey[2][RT / 32];

    const float* xb = x + (size_t)b * (N_ * 3);
    float* ob = out + b * OUTW;
    const int tid = threadIdx.x;
    const int lane = tid & 31, w = tid >> 5;

    // decode stage-1 winners (index 0 is the implicit first sample)
    for (int i = tid; i < NPT1; i += RT) {
        unsigned idx = (i == 0) ? 0u : ((~(unsigned)g_key[b][i - 1]) & (N_ - 1));
        gid[i] = (int)idx;
        sx[i] = xb[(size_t)idx * 3 + 0];
        sy[i] = xb[(size_t)idx * 3 + 1];
        sz[i] = xb[(size_t)idx * 3 + 2];
    }
    __syncthreads();

    int n = NPT1, offs = 0;
    const int cnts[3] = {256, 64, 16};

    for (int st = 0; st < 3; ++st) {
        const int npt = cnts[st];
        for (int i = tid; i < n; i += RT) sdist[i] = 1e10f;
        if (tid == 0) { sel[0] = 0; ob[offs] = (float)gid[0]; }
        __syncthreads();
        float px = sx[0], py = sy[0], pz = sz[0];

        for (int it = 0; it < npt - 1; ++it) {
            const int buf = it & 1;
            ull key = 0ull;
            for (int i = tid; i < n; i += RT) {
                float d  = sqdist(sx[i], sy[i], sz[i], px, py, pz);
                float nd = fminf(sdist[i], d);
                sdist[i] = nd;
                ull k = ((ull)__float_as_uint(nd) << 32) | (unsigned)~i;
                key = kmax64(key, k);
            }
#pragma unroll
            for (int o = 16; o; o >>= 1)
                key = kmax64(key, __shfl_xor_sync(0xffffffffu, key, o));
            if (lane == 0) wkey[buf][w] = key;
            __syncthreads();                               // only bar per iter
            ull best = wkey[buf][0];
#pragma unroll
            for (int ww = 1; ww < RT / 32; ww++) best = kmax64(best, wkey[buf][ww]);
            const int loc = (int)((~(unsigned)best) & (NPT1 - 1));
            if (tid == 0) {
                sel[it + 1] = loc;
                ob[offs + it + 1] = (float)gid[loc];       // float32 output
            }
            px = sx[loc]; py = sy[loc]; pz = sz[loc];      // broadcast LDS
        }
        __syncthreads();                                   // sel[] ready

        // compact the selected npt points to the front for the next stage
        for (int i = tid; i < npt; i += RT) {
            int s2 = sel[i];
            tx[i] = sx[s2]; ty[i] = sy[s2]; tz[i] = sz[s2]; tg[i] = gid[s2];
        }
        __syncthreads();
        for (int i = tid; i < npt; i += RT) {
            sx[i] = tx[i]; sy[i] = ty[i]; sz[i] = tz[i]; gid[i] = tg[i];
        }
        __syncthreads();
        n = npt;
        offs += npt;   // 0 -> 256 -> 320
    }
}

// ---------------- launch ----------------
extern "C" void kernel_launch(void* const* d_in, const int* in_sizes, int n_in,
                              void* d_out, int out_size) {
    (void)in_sizes; (void)n_in; (void)out_size;
    const float* x = (const float*)d_in[0];
    float* out = (float*)d_out;

    cudaFuncSetAttribute(fps_stage1,
                         cudaFuncAttributeMaxDynamicSharedMemorySize,
                         PPB * 3 * sizeof(float));

    fps_stage1<<<B_ * NB, TPB, PPB * 3 * sizeof(float)>>>(x);
    fps_rest<<<B_, RT>>>(x, out);
}